// round 3
// baseline (speedup 1.0000x reference)
#include <cuda_runtime.h>

// ST-BIF IF neuron, T=16 scan. 8 elems/thread, software-pipelined loads
// (t+1 loads issued before t compute), pointer-increment addressing,
// occupancy forced to 5 CTAs/SM.

#define T_STEPS 16
#define POS_MAX 7
#define NEG_MIN (-8)

__device__ __forceinline__ float step_elem(float xin, float rcp, float qth,
                                           float& q, int& a)
{
    q += xin * rcp;                  // qth = 0.5 -> rcp = 2.0 exact
    bool sp = (q - 1.0f >= 0.0f) && (a < POS_MAX);
    bool ng = (q < 0.0f) && (a > NEG_MIN);
    a += sp ? 1 : (ng ? -1 : 0);
    q -= sp ? 1.0f : (ng ? -1.0f : 0.0f);
    return sp ? qth : (ng ? -qth : 0.0f);
}

__global__ void __launch_bounds__(256, 5) ifneuron_kernel(
    const float* __restrict__ x,
    const float* __restrict__ qth_ptr,
    float* __restrict__ out,
    int S)   // spatial size (B*N*D), multiple of 8
{
    int idx = (blockIdx.x * blockDim.x + threadIdx.x) * 8;
    if (idx >= S) return;

    const float qth = __ldg(qth_ptr);
    const float rcp = 1.0f / qth;

    float q[8];
    int   a[8];
    #pragma unroll
    for (int i = 0; i < 8; i++) { q[i] = 0.5f; a[i] = 0; }

    const float* xp = x + idx;
    float*       op = out + idx;

    // prologue: load t=0
    float4 xa = __ldcs(reinterpret_cast<const float4*>(xp));
    float4 xb = __ldcs(reinterpret_cast<const float4*>(xp + 4));

    #pragma unroll
    for (int t = 0; t < T_STEPS; t++) {
        float4 na, nb;
        if (t + 1 < T_STEPS) {
            na = __ldcs(reinterpret_cast<const float4*>(xp + S));
            nb = __ldcs(reinterpret_cast<const float4*>(xp + S + 4));
        }

        float4 oa, ob;
        oa.x = step_elem(xa.x, rcp, qth, q[0], a[0]);
        oa.y = step_elem(xa.y, rcp, qth, q[1], a[1]);
        oa.z = step_elem(xa.z, rcp, qth, q[2], a[2]);
        oa.w = step_elem(xa.w, rcp, qth, q[3], a[3]);
        ob.x = step_elem(xb.x, rcp, qth, q[4], a[4]);
        ob.y = step_elem(xb.y, rcp, qth, q[5], a[5]);
        ob.z = step_elem(xb.z, rcp, qth, q[6], a[6]);
        ob.w = step_elem(xb.w, rcp, qth, q[7], a[7]);

        __stcs(reinterpret_cast<float4*>(op), oa);
        __stcs(reinterpret_cast<float4*>(op + 4), ob);

        xa = na; xb = nb;
        xp += S; op += S;
    }
}

extern "C" void kernel_launch(void* const* d_in, const int* in_sizes, int n_in,
                              void* d_out, int out_size)
{
    const float* x   = (const float*)d_in[0];
    const float* qth = (const float*)d_in[1];
    float* out       = (float*)d_out;

    int total = in_sizes[0];          // T * S
    int S = total / T_STEPS;          // 9,633,792
    int nthreads = S / 8;
    int block = 256;
    int grid = (nthreads + block - 1) / block;

    ifneuron_kernel<<<grid, block>>>(x, qth, out, S);
}

// round 4
// speedup vs baseline: 1.0221x; 1.0221x over previous
#include <cuda_runtime.h>

// ST-BIF IF neuron, T=16 scan. R2 structure (ptxas-scheduled loads),
// slimmed register footprint: outputs overwrite input regs, float acc,
// single select chain per element. Target 5 CTAs/SM.

#define T_STEPS 16
#define POS_MAX 7.0f
#define NEG_MIN (-8.0f)

__device__ __forceinline__ void step_elem(float& v, float rcp, float qth,
                                          float& q, float& a)
{
    q += v * rcp;                    // qth = 0.5 -> rcp = 2.0 exact
    bool sp = (q - 1.0f >= 0.0f) && (a < POS_MAX);
    bool ng = (q < 0.0f) && (a > NEG_MIN);
    float cur = sp ? 1.0f : (ng ? -1.0f : 0.0f);
    a += cur;
    q -= cur;
    v = cur * qth;                   // output overwrites input register
}

__global__ void __launch_bounds__(256, 5) ifneuron_kernel(
    const float* __restrict__ x,
    const float* __restrict__ qth_ptr,
    float* __restrict__ out,
    int S)   // spatial size (B*N*D), multiple of 8
{
    int idx = (blockIdx.x * blockDim.x + threadIdx.x) * 8;
    if (idx >= S) return;

    const float qth = __ldg(qth_ptr);
    const float rcp = 1.0f / qth;

    float q[8];
    float a[8];
    #pragma unroll
    for (int i = 0; i < 8; i++) { q[i] = 0.5f; a[i] = 0.0f; }

    #pragma unroll
    for (int t = 0; t < T_STEPS; t++) {
        const float* xp = x + (size_t)t * S + idx;
        float4 xa = __ldcs(reinterpret_cast<const float4*>(xp));
        float4 xb = __ldcs(reinterpret_cast<const float4*>(xp + 4));

        step_elem(xa.x, rcp, qth, q[0], a[0]);
        step_elem(xa.y, rcp, qth, q[1], a[1]);
        step_elem(xa.z, rcp, qth, q[2], a[2]);
        step_elem(xa.w, rcp, qth, q[3], a[3]);
        step_elem(xb.x, rcp, qth, q[4], a[4]);
        step_elem(xb.y, rcp, qth, q[5], a[5]);
        step_elem(xb.z, rcp, qth, q[6], a[6]);
        step_elem(xb.w, rcp, qth, q[7], a[7]);

        float* op = out + (size_t)t * S + idx;
        __stcs(reinterpret_cast<float4*>(op), xa);
        __stcs(reinterpret_cast<float4*>(op + 4), xb);
    }
}

extern "C" void kernel_launch(void* const* d_in, const int* in_sizes, int n_in,
                              void* d_out, int out_size)
{
    const float* x   = (const float*)d_in[0];
    const float* qth = (const float*)d_in[1];
    float* out       = (float*)d_out;

    int total = in_sizes[0];          // T * S
    int S = total / T_STEPS;          // 9,633,792
    int nthreads = S / 8;
    int block = 256;
    int grid = (nthreads + block - 1) / block;

    ifneuron_kernel<<<grid, block>>>(x, qth, out, S);
}